// round 11
// baseline (speedup 1.0000x reference)
#include <cuda_runtime.h>
#include <math.h>

#define N_SAMPLES 262144
#define N_QUADS   (N_SAMPLES / 4)                 // 65536
#define N_K       128
#define N_STEPS   1024
#define BINS      8192
#define DENOM     (2 * BINS)                      // 16384: angle = 2pi*q/DENOM
#define NBLOCKS   148                             // <= SM count -> co-resident
#define THREADS   1024
#define NWARPS    (THREADS / 32)                  // 32
#define N_INTERVALS 1025
#define TWO_PI    6.2831855f

typedef unsigned long long u64;

// Histogram: per bin, high 32 = n_total, low 32 = n_positive. Zero-initialized
// at load; each launch restores zeros in P3 (after the last read).
__device__ u64   g_hist[BINS];
// Coefficients: [k-1][4] = (tot_s, tot_c, pos_s, pos_c), plus [512] = npos
__device__ float g_coef[4 * N_K + 1];
// Per-block AUC partial sums
__device__ float g_aucA[NBLOCKS], g_aucB[NBLOCKS];
// Barrier / completion counters (self-reset each launch)
__device__ unsigned int g_bar[3] = {0, 0, 0};

// Light grid barrier: release-add + acquire-poll (no threadfence / L1 flush).
__device__ __forceinline__ void gbar(unsigned int* cnt, unsigned int target)
{
    __syncthreads();
    if (threadIdx.x == 0) {
        unsigned int old;
        asm volatile("atom.release.gpu.global.add.u32 %0, [%1], %2;"
                     : "=r"(old) : "l"(cnt), "r"(1u) : "memory");
        unsigned int v;
        do {
            asm volatile("ld.acquire.gpu.global.u32 %0, [%1];"
                         : "=r"(v) : "l"(cnt) : "memory");
        } while (v < target);
    }
    __syncthreads();
}

// ---------------------------------------------------------------------------
// Single fused kernel, 148 blocks x 1024 threads (1/SM, co-resident).
//  P1: histogram via one packed u64 RED per sample            -> barrier A
//  P2: harmonic-per-block DFT: block b<128 sums all 8192 bins for harmonic
//      b+1 and writes g_coef[4b..4b+3]; block 128 sums npos   -> barrier B
//  P3: zero own hist slice; coefficients + CDF points (1/warp) + local
//      partial AUC -> counter; last block folds 148 partials -> out.
// ---------------------------------------------------------------------------
__global__ void __launch_bounds__(THREADS, 1)
fused_kernel(const float4* __restrict__ scores4, const uint4* __restrict__ targets4,
             float* __restrict__ out)
{
    const int bid  = blockIdx.x;
    const int tid  = threadIdx.x;
    const int lane = tid & 31, wid = tid >> 5;

    // ---------------- P1: histogram ----------------
    {
        const int qs = (bid * N_QUADS) / NBLOCKS;
        const int qe = ((bid + 1) * N_QUADS) / NBLOCKS;
        for (int i = qs + tid; i < qe; i += THREADS) {
            const float4 sv = scores4[i];
            const uint4  tv = targets4[i];
            const float scs[4] = {sv.x, sv.y, sv.z, sv.w};
            const unsigned ms[4] = {tv.x, tv.y, tv.z, tv.w};
#pragma unroll
            for (int e = 0; e < 4; ++e) {
                int b = (int)(scs[e] * (float)BINS);
                b = (b > BINS - 1) ? (BINS - 1) : ((b < 0) ? 0 : b);
                const u64 add = (1ull << 32) | (u64)(ms[e] ? 1u : 0u);
                atomicAdd(&g_hist[b], add);
            }
        }
    }
    gbar(&g_bar[0], NBLOCKS);

    // ---------------- P2: harmonic-per-block DFT ----------------
    __shared__ float rsum[NWARPS][4];
    if (bid < N_K) {
        const int k = bid + 1;
        float ts = 0.f, tc = 0.f, ps = 0.f, pc = 0.f;
#pragma unroll
        for (int j = 0; j < BINS / THREADS; ++j) {
            const int bin = tid + j * THREADS;
            const u64 h = g_hist[bin];
            const float nt = (float)(unsigned)(h >> 32);
            const float np = (float)(unsigned)(h & 0xffffffffu);
            const int q = (k * (2 * bin + 1)) & (DENOM - 1);  // exact mod 2pi
            const float ang = (float)q * (TWO_PI / (float)DENOM);
            float s, c;
            __sincosf(ang, &s, &c);
            ts = fmaf(nt, s, ts);
            tc = fmaf(nt, c, tc);
            ps = fmaf(np, s, ps);
            pc = fmaf(np, c, pc);
        }
#pragma unroll
        for (int o = 16; o > 0; o >>= 1) {
            ts += __shfl_down_sync(0xffffffffu, ts, o);
            tc += __shfl_down_sync(0xffffffffu, tc, o);
            ps += __shfl_down_sync(0xffffffffu, ps, o);
            pc += __shfl_down_sync(0xffffffffu, pc, o);
        }
        if (lane == 0) {
            rsum[wid][0] = ts; rsum[wid][1] = tc;
            rsum[wid][2] = ps; rsum[wid][3] = pc;
        }
        __syncthreads();
        if (tid < 4) {
            float s = 0.f;
#pragma unroll
            for (int w = 0; w < NWARPS; ++w) s += rsum[w][tid];
            g_coef[4 * bid + tid] = s;
        }
    } else if (bid == N_K) {
        float np = 0.f;
#pragma unroll
        for (int j = 0; j < BINS / THREADS; ++j) {
            const u64 h = g_hist[tid + j * THREADS];
            np += (float)(unsigned)(h & 0xffffffffu);
        }
#pragma unroll
        for (int o = 16; o > 0; o >>= 1)
            np += __shfl_down_sync(0xffffffffu, np, o);
        if (lane == 0) rsum[wid][0] = np;
        __syncthreads();
        if (tid == 0) {
            float s = 0.f;
#pragma unroll
            for (int w = 0; w < NWARPS; ++w) s += rsum[w][0];
            g_coef[4 * N_K] = s;
        }
    }
    gbar(&g_bar[1], NBLOCKS);

    // ---------------- P3: zero hist, coefficients, CDF, partial AUC ----------------
    // zero own slice (hist is dead after barrier B)
    {
        const int zs = (bid * BINS) / NBLOCKS;
        const int ze = ((bid + 1) * BINS) / NBLOCKS;
        for (int b = zs + tid; b < ze; b += THREADS) g_hist[b] = 0ull;
    }

    __shared__ float sisp[N_K], sicp[N_K], sisn[N_K], sicn[N_K];
    __shared__ float ptp[9], ptn[9];
    if (tid < N_K) {
        const float EPS = 1.1920929e-7f;
        const int k = tid + 1;
        const float tpk = TWO_PI * (float)k;
        const float npos = g_coef[4 * N_K];
        const float nneg = (float)N_SAMPLES - npos;

        // sinc correction for uniform-within-bin
        const float x = (float)k * (3.14159265358979f / (float)BINS);
        const float snc = __sinf(x) / x;

        const float St = g_coef[tid * 4 + 0];
        const float Ct = g_coef[tid * 4 + 1];
        const float Sp = g_coef[tid * 4 + 2];
        const float Cp = g_coef[tid * 4 + 3];

        const float ps  = (npos < EPS) ? 0.f : (Sp * snc) / fmaxf(npos, EPS);
        const float pc  = (npos < EPS) ? 0.f : (Cp * snc) / fmaxf(npos, EPS);
        const float nsn = (nneg < EPS) ? 0.f : ((St - Sp) * snc) / fmaxf(nneg, EPS);
        const float ncn = (nneg < EPS) ? 0.f : ((Ct - Cp) * snc) / fmaxf(nneg, EPS);

        sisp[tid] =  pc / tpk;
        sicp[tid] = -ps / tpk;
        sisn[tid] =  ncn / tpk;
        sicn[tid] = -nsn / tpk;
    }
    __syncthreads();

    // Block handles intervals [i0, i1); needs points i0 .. i1 (<= 8 points).
    const int i0 = (bid * N_INTERVALS) / NBLOCKS;
    const int i1 = ((bid + 1) * N_INTERVALS) / NBLOCKS;
    const int npts = i1 - i0 + 1;
    {
        const int j = i0 + wid;                   // point index this warp computes
        if (wid < npts) {
            float vp, vn;
            if (j == 0)            { vp = 1.f; vn = 1.f; }
            else if (j == 1025)    { vp = 0.f; vn = 0.f; }
            else {
                const float thr = (float)(j - 1) / 1023.0f;
                float cdfp = 0.f, cdfn = 0.f;
#pragma unroll
                for (int i = 0; i < 4; ++i) {
                    const int k = lane + i * 32;
                    const float tpk = TWO_PI * (float)(k + 1);
                    float s, c;
                    __sincosf(thr * tpk, &s, &c);
                    cdfp = fmaf(s, sisp[k], fmaf(c, sicp[k], cdfp));
                    cdfn = fmaf(s, sisn[k], fmaf(c, sicn[k], cdfn));
                }
#pragma unroll
                for (int o = 16; o > 0; o >>= 1) {
                    cdfp += __shfl_down_sync(0xffffffffu, cdfp, o);
                    cdfn += __shfl_down_sync(0xffffffffu, cdfn, o);
                }
                vp = 1.0f - 0.5f * (cdfp + 0.5f);
                vn = 1.0f - 0.5f * (cdfn + 0.5f);
            }
            if (lane == 0) { ptp[wid] = vp; ptn[wid] = vn; }
        }
    }
    __syncthreads();
    if (tid == 0) {
        float tp = 0.f, tn = 0.f;
        for (int i = 0; i < npts - 1; ++i) {
            tp = fmaf(ptp[i], ptn[i] - ptn[i + 1], tp);
            tn = fmaf(ptn[i], ptp[i + 1] - ptp[i], tn);
        }
        g_aucA[bid] = tp;
        g_aucB[bid] = tn;
    }

    // ---------------- completion counter; last block finishes ----------------
    __syncthreads();
    __shared__ unsigned int is_last;
    if (tid == 0) {
        unsigned int old;
        asm volatile("atom.release.gpu.global.add.u32 %0, [%1], %2;"
                     : "=r"(old) : "l"(&g_bar[2]), "r"(1u) : "memory");
        is_last = (old == NBLOCKS - 1) ? 1u : 0u;
    }
    __syncthreads();
    if (!is_last) return;
    if (tid == 0) {
        unsigned int v;
        asm volatile("ld.acquire.gpu.global.u32 %0, [%1];"
                     : "=r"(v) : "l"(&g_bar[2]) : "memory");
        (void)v;
    }
    __syncthreads();

    if (wid == 0) {
        float a = 0.f, b = 0.f;
        for (int i = lane; i < NBLOCKS; i += 32) { a += g_aucA[i]; b += g_aucB[i]; }
#pragma unroll
        for (int o = 16; o > 0; o >>= 1) {
            a += __shfl_down_sync(0xffffffffu, a, o);
            b += __shfl_down_sync(0xffffffffu, b, o);
        }
        if (lane == 0) {
            out[0] = 0.5f * (a + (1.0f + b));
            g_bar[0] = 0; g_bar[1] = 0; g_bar[2] = 0;
        }
    }
}

extern "C" void kernel_launch(void* const* d_in, const int* in_sizes, int n_in,
                              void* d_out, int out_size)
{
    (void)in_sizes; (void)n_in; (void)out_size;
    const float4* scores4  = (const float4*)d_in[0];
    const uint4*  targets4 = (const uint4*)d_in[1];
    float* out = (float*)d_out;

    fused_kernel<<<NBLOCKS, THREADS>>>(scores4, targets4, out);
}

// round 12
// speedup vs baseline: 1.0347x; 1.0347x over previous
#include <cuda_runtime.h>
#include <math.h>

#define N_SAMPLES 262144
#define N_QUADS   (N_SAMPLES / 4)                 // 65536
#define N_K       128
#define N_STEPS   1024
#define BINS      8192
#define DENOM     (2 * BINS)                      // 16384: angle = 2pi*q/DENOM
#define NBLOCKS   148                             // <= SM count -> co-resident
#define THREADS   512
#define NWARPS    (THREADS / 32)                  // 16
#define N_INTERVALS 1025
#define TWO_PI    6.2831855f

typedef unsigned long long u64;

// Histogram: per bin, high 32 = n_total, low 32 = n_positive. Zero-initialized
// at load; each launch restores zeros in P3 (after the last read).
__device__ __align__(16) u64 g_hist[BINS];
// Coefficients: [k-1][4] = (tot_s, tot_c, pos_s, pos_c), plus [512] = npos
__device__ float g_coef[4 * N_K + 1];
// Per-block AUC partial sums
__device__ float g_aucA[NBLOCKS], g_aucB[NBLOCKS];
// Split barrier counters (16-way to avoid same-address atomic serialization).
__device__ unsigned int g_barA[16], g_barB[16], g_barF[16];

// Arrival: release-add on counter (bid & 15). Poll: warp 0, lane i acquires
// counter i (i<16), 32-lane butterfly sum -> everyone sees total.
__device__ __forceinline__ void gbar_split(unsigned int* cnt16)
{
    __syncthreads();
    const int tid = threadIdx.x;
    if (tid == 0) {
        asm volatile("red.release.gpu.global.add.u32 [%0], %1;"
                     :: "l"(cnt16 + (blockIdx.x & 15)), "r"(1u) : "memory");
    }
    if (tid < 32) {
        unsigned int s;
        do {
            unsigned int v = 0;
            if (tid < 16)
                asm volatile("ld.acquire.gpu.global.u32 %0, [%1];"
                             : "=r"(v) : "l"(cnt16 + tid) : "memory");
            s = v;
#pragma unroll
            for (int o = 16; o > 0; o >>= 1)
                s += __shfl_xor_sync(0xffffffffu, s, o);
        } while (s < NBLOCKS);
    }
    __syncthreads();
}

// ---------------------------------------------------------------------------
// Single fused kernel, 148 blocks x 512 threads (1/SM, co-resident).
//  P1: histogram via one packed u64 red.relaxed per sample     -> split bar A
//  P2: harmonic-per-block DFT (vectorized 16B hist reads)      -> split bar B
//  P3: zero own hist slice; coefficients + CDF points (1/warp) + local
//      partial AUC -> split arrivals F; block 0 polls F, folds -> out, resets.
// ---------------------------------------------------------------------------
__global__ void __launch_bounds__(THREADS, 1)
fused_kernel(const float4* __restrict__ scores4, const uint4* __restrict__ targets4,
             float* __restrict__ out)
{
    const int bid  = blockIdx.x;
    const int tid  = threadIdx.x;
    const int lane = tid & 31, wid = tid >> 5;

    // ---------------- P1: histogram ----------------
    {
        const int qs = (bid * N_QUADS) / NBLOCKS;
        const int qe = ((bid + 1) * N_QUADS) / NBLOCKS;
        for (int i = qs + tid; i < qe; i += THREADS) {
            const float4 sv = scores4[i];
            const uint4  tv = targets4[i];
            const float scs[4] = {sv.x, sv.y, sv.z, sv.w};
            const unsigned ms[4] = {tv.x, tv.y, tv.z, tv.w};
#pragma unroll
            for (int e = 0; e < 4; ++e) {
                int b = (int)(scs[e] * (float)BINS);
                b = (b > BINS - 1) ? (BINS - 1) : ((b < 0) ? 0 : b);
                const u64 add = (1ull << 32) | (u64)(ms[e] ? 1u : 0u);
                asm volatile("red.relaxed.gpu.global.add.u64 [%0], %1;"
                             :: "l"(&g_hist[b]), "l"(add) : "memory");
            }
        }
    }
    gbar_split(g_barA);

    // ---------------- P2: harmonic-per-block DFT ----------------
    __shared__ float rsum[NWARPS][4];
    if (bid < N_K) {
        const int k = bid + 1;
        float ts = 0.f, tc = 0.f, ps = 0.f, pc = 0.f;
        const ulonglong2* h2p = (const ulonglong2*)g_hist;
#pragma unroll
        for (int j = 0; j < BINS / (2 * THREADS); ++j) {     // 8 iters
            const int pr = tid + j * THREADS;                // bin pair index
            const ulonglong2 h2 = h2p[pr];
#pragma unroll
            for (int half = 0; half < 2; ++half) {
                const u64 h = half ? h2.y : h2.x;
                const int bin = 2 * pr + half;
                const float nt = (float)(unsigned)(h >> 32);
                const float np = (float)(unsigned)(h & 0xffffffffu);
                const int q = (k * (2 * bin + 1)) & (DENOM - 1);
                const float ang = (float)q * (TWO_PI / (float)DENOM);
                float s, c;
                __sincosf(ang, &s, &c);
                ts = fmaf(nt, s, ts);
                tc = fmaf(nt, c, tc);
                ps = fmaf(np, s, ps);
                pc = fmaf(np, c, pc);
            }
        }
#pragma unroll
        for (int o = 16; o > 0; o >>= 1) {
            ts += __shfl_down_sync(0xffffffffu, ts, o);
            tc += __shfl_down_sync(0xffffffffu, tc, o);
            ps += __shfl_down_sync(0xffffffffu, ps, o);
            pc += __shfl_down_sync(0xffffffffu, pc, o);
        }
        if (lane == 0) {
            rsum[wid][0] = ts; rsum[wid][1] = tc;
            rsum[wid][2] = ps; rsum[wid][3] = pc;
        }
        __syncthreads();
        if (tid < 4) {
            float s = 0.f;
#pragma unroll
            for (int w = 0; w < NWARPS; ++w) s += rsum[w][tid];
            g_coef[4 * bid + tid] = s;
        }
    } else if (bid == N_K) {
        float np = 0.f;
#pragma unroll
        for (int j = 0; j < BINS / THREADS; ++j) {
            const u64 h = g_hist[tid + j * THREADS];
            np += (float)(unsigned)(h & 0xffffffffu);
        }
#pragma unroll
        for (int o = 16; o > 0; o >>= 1)
            np += __shfl_down_sync(0xffffffffu, np, o);
        if (lane == 0) rsum[wid][0] = np;
        __syncthreads();
        if (tid == 0) {
            float s = 0.f;
#pragma unroll
            for (int w = 0; w < NWARPS; ++w) s += rsum[w][0];
            g_coef[4 * N_K] = s;
        }
    }
    gbar_split(g_barB);

    // ---------------- P3: zero hist, coefficients, CDF, partial AUC ----------------
    {
        const int zs = (bid * BINS) / NBLOCKS;
        const int ze = ((bid + 1) * BINS) / NBLOCKS;
        for (int b = zs + tid; b < ze; b += THREADS) g_hist[b] = 0ull;
    }

    __shared__ float sisp[N_K], sicp[N_K], sisn[N_K], sicn[N_K];
    __shared__ float ptp[9], ptn[9];
    if (tid < N_K) {
        const float EPS = 1.1920929e-7f;
        const int k = tid + 1;
        const float tpk = TWO_PI * (float)k;
        const float npos = g_coef[4 * N_K];
        const float nneg = (float)N_SAMPLES - npos;

        // sinc correction for uniform-within-bin
        const float x = (float)k * (3.14159265358979f / (float)BINS);
        const float snc = __sinf(x) / x;

        const float St = g_coef[tid * 4 + 0];
        const float Ct = g_coef[tid * 4 + 1];
        const float Sp = g_coef[tid * 4 + 2];
        const float Cp = g_coef[tid * 4 + 3];

        const float ps  = (npos < EPS) ? 0.f : (Sp * snc) / fmaxf(npos, EPS);
        const float pc  = (npos < EPS) ? 0.f : (Cp * snc) / fmaxf(npos, EPS);
        const float nsn = (nneg < EPS) ? 0.f : ((St - Sp) * snc) / fmaxf(nneg, EPS);
        const float ncn = (nneg < EPS) ? 0.f : ((Ct - Cp) * snc) / fmaxf(nneg, EPS);

        sisp[tid] =  pc / tpk;
        sicp[tid] = -ps / tpk;
        sisn[tid] =  ncn / tpk;
        sicn[tid] = -nsn / tpk;
    }
    __syncthreads();

    // Block handles intervals [i0, i1); needs points i0 .. i1 (<= 8 points).
    const int i0 = (bid * N_INTERVALS) / NBLOCKS;
    const int i1 = ((bid + 1) * N_INTERVALS) / NBLOCKS;
    const int npts = i1 - i0 + 1;
    {
        const int j = i0 + wid;                   // point index this warp computes
        if (wid < npts) {
            float vp, vn;
            if (j == 0)            { vp = 1.f; vn = 1.f; }
            else if (j == 1025)    { vp = 0.f; vn = 0.f; }
            else {
                const float thr = (float)(j - 1) / 1023.0f;
                float cdfp = 0.f, cdfn = 0.f;
#pragma unroll
                for (int i = 0; i < 4; ++i) {
                    const int k = lane + i * 32;
                    const float tpk = TWO_PI * (float)(k + 1);
                    float s, c;
                    __sincosf(thr * tpk, &s, &c);
                    cdfp = fmaf(s, sisp[k], fmaf(c, sicp[k], cdfp));
                    cdfn = fmaf(s, sisn[k], fmaf(c, sicn[k], cdfn));
                }
#pragma unroll
                for (int o = 16; o > 0; o >>= 1) {
                    cdfp += __shfl_down_sync(0xffffffffu, cdfp, o);
                    cdfn += __shfl_down_sync(0xffffffffu, cdfn, o);
                }
                vp = 1.0f - 0.5f * (cdfp + 0.5f);
                vn = 1.0f - 0.5f * (cdfn + 0.5f);
            }
            if (lane == 0) { ptp[wid] = vp; ptn[wid] = vn; }
        }
    }
    __syncthreads();
    if (tid == 0) {
        float tp = 0.f, tn = 0.f;
        for (int i = 0; i < npts - 1; ++i) {
            tp = fmaf(ptp[i], ptn[i] - ptn[i + 1], tp);
            tn = fmaf(ptn[i], ptp[i + 1] - ptp[i], tn);
        }
        g_aucA[bid] = tp;
        g_aucB[bid] = tn;
    }

    // ---------------- Final: split arrivals; block 0 polls & folds ----------------
    __syncthreads();
    if (tid == 0) {
        asm volatile("red.release.gpu.global.add.u32 [%0], %1;"
                     :: "l"(g_barF + (bid & 15)), "r"(1u) : "memory");
    }
    if (bid != 0) return;

    if (tid < 32) {
        unsigned int s;
        do {
            unsigned int v = 0;
            if (tid < 16)
                asm volatile("ld.acquire.gpu.global.u32 %0, [%1];"
                             : "=r"(v) : "l"(g_barF + tid) : "memory");
            s = v;
#pragma unroll
            for (int o = 16; o > 0; o >>= 1)
                s += __shfl_xor_sync(0xffffffffu, s, o);
        } while (s < NBLOCKS);
    }
    __syncthreads();

    if (wid == 0) {
        float a = 0.f, b = 0.f;
        for (int i = lane; i < NBLOCKS; i += 32) { a += g_aucA[i]; b += g_aucB[i]; }
#pragma unroll
        for (int o = 16; o > 0; o >>= 1) {
            a += __shfl_down_sync(0xffffffffu, a, o);
            b += __shfl_down_sync(0xffffffffu, b, o);
        }
        if (lane == 0) out[0] = 0.5f * (a + (1.0f + b));
    }
    // Reset all barrier counters for the next graph replay (all other blocks
    // have exited: their F-arrival implies they passed A and B polls).
    if (tid < 16) { g_barA[tid] = 0; g_barB[tid] = 0; g_barF[tid] = 0; }
}

extern "C" void kernel_launch(void* const* d_in, const int* in_sizes, int n_in,
                              void* d_out, int out_size)
{
    (void)in_sizes; (void)n_in; (void)out_size;
    const float4* scores4  = (const float4*)d_in[0];
    const uint4*  targets4 = (const uint4*)d_in[1];
    float* out = (float*)d_out;

    fused_kernel<<<NBLOCKS, THREADS>>>(scores4, targets4, out);
}

// round 13
// speedup vs baseline: 1.1380x; 1.0998x over previous
#include <cuda_runtime.h>
#include <math.h>

#define N_SAMPLES 262144
#define N_QUADS   (N_SAMPLES / 4)                 // 65536
#define N_K       128
#define N_STEPS   1024
#define BINS      8192
#define DENOM     (2 * BINS)                      // 16384: angle = 2pi*q/DENOM
#define NBLOCKS   148                             // <= SM count -> co-resident
#define THREADS   512
#define NWARPS    (THREADS / 32)                  // 16
#define N_INTERVALS 1025
#define TWO_PI    6.2831855f
#define FP_SCALE  1.099511627776e12f              // 2^40
#define FP_INV    9.094947017729282e-13f          // 2^-40

typedef unsigned long long u64;

// Histogram: per bin, high 32 = n_total, low 32 = n_positive. Zero-initialized
// at load; each launch restores zeros in P3 (after the last read).
__device__ __align__(16) u64 g_hist[BINS];
// Coefficients: [k-1][4] = (tot_s, tot_c, pos_s, pos_c), plus [512] = npos
__device__ float g_coef[4 * N_K + 1];
// Fixed-point AUC accumulators (deterministic integer adds)
__device__ u64 g_fpA = 0, g_fpB = 0;
// Completion counter for the final fold
__device__ unsigned int g_fin = 0;
// Split barrier counters: 16 counters, each on its own 128B line (stride 32 u32)
__device__ unsigned int g_barA[16 * 32], g_barB[16 * 32];

// Arrival: release-add on counter (bid & 15), own cache line. Poll: warp 0,
// lane i (<16) acquires counter i*32, butterfly sum, nanosleep backoff.
__device__ __forceinline__ void gbar_split(unsigned int* cnt16)
{
    __syncthreads();
    const int tid = threadIdx.x;
    if (tid == 0) {
        asm volatile("red.release.gpu.global.add.u32 [%0], %1;"
                     :: "l"(cnt16 + (blockIdx.x & 15) * 32), "r"(1u) : "memory");
    }
    if (tid < 32) {
        for (;;) {
            unsigned int v = 0;
            if (tid < 16)
                asm volatile("ld.acquire.gpu.global.u32 %0, [%1];"
                             : "=r"(v) : "l"(cnt16 + tid * 32) : "memory");
            unsigned int s = v;
#pragma unroll
            for (int o = 16; o > 0; o >>= 1)
                s += __shfl_xor_sync(0xffffffffu, s, o);
            if (s >= NBLOCKS) break;
            __nanosleep(64);
        }
    }
    __syncthreads();
}

// ---------------------------------------------------------------------------
// Single fused kernel, 148 blocks x 512 threads (1/SM, co-resident).
//  P1: histogram, exactly one quad per thread (packed u64 red.relaxed)
//  P2: harmonic-per-block DFT (blocks 0..127), npos (block 128)
//  P3: zero own hist slice; coefficients + CDF points (1/warp) + partial AUC
//      folded via fixed-point u64 atomics; last arrival writes out + resets.
// ---------------------------------------------------------------------------
__global__ void __launch_bounds__(THREADS, 1)
fused_kernel(const float4* __restrict__ scores4, const uint4* __restrict__ targets4,
             float* __restrict__ out)
{
    const int bid  = blockIdx.x;
    const int tid  = threadIdx.x;
    const int lane = tid & 31, wid = tid >> 5;

    // ---------------- P1: histogram (one quad per thread) ----------------
    {
        const int i = bid * THREADS + tid;
        if (i < N_QUADS) {
            const float4 sv = scores4[i];
            const uint4  tv = targets4[i];
            const float scs[4] = {sv.x, sv.y, sv.z, sv.w};
            const unsigned ms[4] = {tv.x, tv.y, tv.z, tv.w};
#pragma unroll
            for (int e = 0; e < 4; ++e) {
                int b = (int)(scs[e] * (float)BINS);
                b = (b > BINS - 1) ? (BINS - 1) : ((b < 0) ? 0 : b);
                const u64 add = (1ull << 32) | (u64)(ms[e] ? 1u : 0u);
                asm volatile("red.relaxed.gpu.global.add.u64 [%0], %1;"
                             :: "l"(&g_hist[b]), "l"(add) : "memory");
            }
        }
    }
    gbar_split(g_barA);

    // ---------------- P2: harmonic-per-block DFT ----------------
    __shared__ float rsum[NWARPS][4];
    if (bid < N_K) {
        const int k = bid + 1;
        float ts = 0.f, tc = 0.f, ps = 0.f, pc = 0.f;
        const ulonglong2* h2p = (const ulonglong2*)g_hist;
#pragma unroll
        for (int j = 0; j < BINS / (2 * THREADS); ++j) {     // 8 iters
            const int pr = tid + j * THREADS;                // bin pair index
            const ulonglong2 h2 = h2p[pr];
#pragma unroll
            for (int half = 0; half < 2; ++half) {
                const u64 h = half ? h2.y : h2.x;
                const int bin = 2 * pr + half;
                const float nt = (float)(unsigned)(h >> 32);
                const float np = (float)(unsigned)(h & 0xffffffffu);
                const int q = (k * (2 * bin + 1)) & (DENOM - 1);
                const float ang = (float)q * (TWO_PI / (float)DENOM);
                float s, c;
                __sincosf(ang, &s, &c);
                ts = fmaf(nt, s, ts);
                tc = fmaf(nt, c, tc);
                ps = fmaf(np, s, ps);
                pc = fmaf(np, c, pc);
            }
        }
#pragma unroll
        for (int o = 16; o > 0; o >>= 1) {
            ts += __shfl_down_sync(0xffffffffu, ts, o);
            tc += __shfl_down_sync(0xffffffffu, tc, o);
            ps += __shfl_down_sync(0xffffffffu, ps, o);
            pc += __shfl_down_sync(0xffffffffu, pc, o);
        }
        if (lane == 0) {
            rsum[wid][0] = ts; rsum[wid][1] = tc;
            rsum[wid][2] = ps; rsum[wid][3] = pc;
        }
        __syncthreads();
        if (tid < 4) {
            float s = 0.f;
#pragma unroll
            for (int w = 0; w < NWARPS; ++w) s += rsum[w][tid];
            g_coef[4 * bid + tid] = s;
        }
    } else if (bid == N_K) {
        float np = 0.f;
#pragma unroll
        for (int j = 0; j < BINS / THREADS; ++j) {
            const u64 h = g_hist[tid + j * THREADS];
            np += (float)(unsigned)(h & 0xffffffffu);
        }
#pragma unroll
        for (int o = 16; o > 0; o >>= 1)
            np += __shfl_down_sync(0xffffffffu, np, o);
        if (lane == 0) rsum[wid][0] = np;
        __syncthreads();
        if (tid == 0) {
            float s = 0.f;
#pragma unroll
            for (int w = 0; w < NWARPS; ++w) s += rsum[w][0];
            g_coef[4 * N_K] = s;
        }
    }
    gbar_split(g_barB);

    // ---------------- P3: zero hist, coefficients, CDF, partial AUC ----------------
    {
        const int zs = (bid * BINS) / NBLOCKS;
        const int ze = ((bid + 1) * BINS) / NBLOCKS;
        for (int b = zs + tid; b < ze; b += THREADS) g_hist[b] = 0ull;
    }

    __shared__ float sisp[N_K], sicp[N_K], sisn[N_K], sicn[N_K];
    __shared__ float ptp[9], ptn[9];
    if (tid < N_K) {
        const float EPS = 1.1920929e-7f;
        const int k = tid + 1;
        const float tpk = TWO_PI * (float)k;
        const float npos = g_coef[4 * N_K];
        const float nneg = (float)N_SAMPLES - npos;

        // sinc correction for uniform-within-bin
        const float x = (float)k * (3.14159265358979f / (float)BINS);
        const float snc = __sinf(x) / x;

        const float St = g_coef[tid * 4 + 0];
        const float Ct = g_coef[tid * 4 + 1];
        const float Sp = g_coef[tid * 4 + 2];
        const float Cp = g_coef[tid * 4 + 3];

        const float ps  = (npos < EPS) ? 0.f : (Sp * snc) / fmaxf(npos, EPS);
        const float pc  = (npos < EPS) ? 0.f : (Cp * snc) / fmaxf(npos, EPS);
        const float nsn = (nneg < EPS) ? 0.f : ((St - Sp) * snc) / fmaxf(nneg, EPS);
        const float ncn = (nneg < EPS) ? 0.f : ((Ct - Cp) * snc) / fmaxf(nneg, EPS);

        sisp[tid] =  pc / tpk;
        sicp[tid] = -ps / tpk;
        sisn[tid] =  ncn / tpk;
        sicn[tid] = -nsn / tpk;
    }
    __syncthreads();

    // Block handles intervals [i0, i1); needs points i0 .. i1 (<= 8 points).
    const int i0 = (bid * N_INTERVALS) / NBLOCKS;
    const int i1 = ((bid + 1) * N_INTERVALS) / NBLOCKS;
    const int npts = i1 - i0 + 1;
    {
        const int j = i0 + wid;
        if (wid < npts) {
            float vp, vn;
            if (j == 0)            { vp = 1.f; vn = 1.f; }
            else if (j == 1025)    { vp = 0.f; vn = 0.f; }
            else {
                const float thr = (float)(j - 1) / 1023.0f;
                float cdfp = 0.f, cdfn = 0.f;
#pragma unroll
                for (int i = 0; i < 4; ++i) {
                    const int k = lane + i * 32;
                    const float tpk = TWO_PI * (float)(k + 1);
                    float s, c;
                    __sincosf(thr * tpk, &s, &c);
                    cdfp = fmaf(s, sisp[k], fmaf(c, sicp[k], cdfp));
                    cdfn = fmaf(s, sisn[k], fmaf(c, sicn[k], cdfn));
                }
#pragma unroll
                for (int o = 16; o > 0; o >>= 1) {
                    cdfp += __shfl_down_sync(0xffffffffu, cdfp, o);
                    cdfn += __shfl_down_sync(0xffffffffu, cdfn, o);
                }
                vp = 1.0f - 0.5f * (cdfp + 0.5f);
                vn = 1.0f - 0.5f * (cdfn + 0.5f);
            }
            if (lane == 0) { ptp[wid] = vp; ptn[wid] = vn; }
        }
    }
    __syncthreads();

    // ---------------- Final fold: fixed-point atomics, last arrival writes ----
    if (tid == 0) {
        float tp = 0.f, tn = 0.f;
        for (int i = 0; i < npts - 1; ++i) {
            tp = fmaf(ptp[i], ptn[i] - ptn[i + 1], tp);
            tn = fmaf(ptn[i], ptp[i + 1] - ptp[i], tn);
        }
        const u64 fa = (u64)(long long)__float2ll_rn(tp * FP_SCALE);
        const u64 fb = (u64)(long long)__float2ll_rn(tn * FP_SCALE);
        asm volatile("red.relaxed.gpu.global.add.u64 [%0], %1;"
                     :: "l"(&g_fpA), "l"(fa) : "memory");
        asm volatile("red.relaxed.gpu.global.add.u64 [%0], %1;"
                     :: "l"(&g_fpB), "l"(fb) : "memory");
        unsigned int old;
        asm volatile("atom.acq_rel.gpu.global.add.u32 %0, [%1], %2;"
                     : "=r"(old) : "l"(&g_fin), "r"(1u) : "memory");
        if (old == NBLOCKS - 1) {
            u64 A, B;
            asm volatile("ld.acquire.gpu.global.u64 %0, [%1];"
                         : "=l"(A) : "l"(&g_fpA) : "memory");
            asm volatile("ld.acquire.gpu.global.u64 %0, [%1];"
                         : "=l"(B) : "l"(&g_fpB) : "memory");
            const float a = (float)(long long)A * FP_INV;
            const float b = (float)(long long)B * FP_INV;
            out[0] = 0.5f * (a + (1.0f + b));
            // Reset all cross-launch state (every block has passed every sync)
            g_fpA = 0; g_fpB = 0; g_fin = 0;
#pragma unroll
            for (int i = 0; i < 16; ++i) {
                g_barA[i * 32] = 0;
                g_barB[i * 32] = 0;
            }
        }
    }
}

extern "C" void kernel_launch(void* const* d_in, const int* in_sizes, int n_in,
                              void* d_out, int out_size)
{
    (void)in_sizes; (void)n_in; (void)out_size;
    const float4* scores4  = (const float4*)d_in[0];
    const uint4*  targets4 = (const uint4*)d_in[1];
    float* out = (float*)d_out;

    fused_kernel<<<NBLOCKS, THREADS>>>(scores4, targets4, out);
}